// round 1
// baseline (speedup 1.0000x reference)
#include <cuda_runtime.h>
#include <math.h>

// Problem constants (from reference setup_inputs)
#define WDIM 512
#define LDIM 512
#define WL   (WDIM * LDIM)   // 262144 pixels
#define NTGT 64

// Scratch (no allocations allowed): double accumulator + precomputed target 2D boxes
__device__ double g_accum;
__device__ float  g_tgt[NTGT * 5];   // minx, miny, maxx, maxy, area

// ---------------------------------------------------------------------------
// Kernel 1: precompute target standup-2D boxes (closed form, no corner loop)
// and zero the accumulator. Single block of 64 threads.
// ---------------------------------------------------------------------------
__global__ void prep_kernel(const float* __restrict__ target) {
    int m = threadIdx.x;
    if (m == 0) g_accum = 0.0;
    if (m < NTGT) {
        const float* t = target + m * 7;
        float X = t[0], Y = t[1];
        float w = t[4], l = t[5];
        float yaw = t[6];
        float c, s;
        __sincosf(yaw, &s, &c);
        // corner_x = X + cx*c - cy*s, cx=±l/2, cy=±w/2 (independent signs)
        float ex = 0.5f * (fabsf(c) * l + fabsf(s) * w);
        float ey = 0.5f * (fabsf(s) * l + fabsf(c) * w);
        g_tgt[m * 5 + 0] = X - ex;
        g_tgt[m * 5 + 1] = Y - ey;
        g_tgt[m * 5 + 2] = X + ex;
        g_tgt[m * 5 + 3] = Y + ey;
        g_tgt[m * 5 + 4] = (2.0f * ex) * (2.0f * ey);   // area_g
    }
}

// ---------------------------------------------------------------------------
// Kernel 2: main pass. One thread per pixel, both anchors (a=0,1) fused so the
// 64-target loop is walked once per pixel for two boxes.
// ---------------------------------------------------------------------------
__global__ __launch_bounds__(256) void loss_kernel(
    const float* __restrict__ psm,   // [2, W, L]
    const float* __restrict__ rm,    // [14, W, L]
    const float* __restrict__ anc,   // [W, L, 2, 7]
    const float* __restrict__ Tm)    // [4, 4]
{
    __shared__ float4 st_box[NTGT];
    __shared__ float  st_area[NTGT];

    if (threadIdx.x < NTGT) {
        int m = threadIdx.x;
        st_box[m]  = make_float4(g_tgt[m * 5 + 0], g_tgt[m * 5 + 1],
                                 g_tgt[m * 5 + 2], g_tgt[m * 5 + 3]);
        st_area[m] = g_tgt[m * 5 + 4];
    }
    __syncthreads();

    int pix = blockIdx.x * blockDim.x + threadIdx.x;   // exact grid: WL threads

    const float T00 = Tm[0], T01 = Tm[1], T02 = Tm[2], T03 = Tm[3];
    const float T10 = Tm[4], T11 = Tm[5], T12 = Tm[6], T13 = Tm[7];

    const float* A = anc + (size_t)pix * 14;

    float px1[2], py1[2], px2[2], py2[2], area_t[2], wlog[2];

#pragma unroll
    for (int a = 0; a < 2; a++) {
        // prob
        float xlogit = psm[a * WL + pix];
        float prob = 1.0f / (1.0f + __expf(-xlogit));

        // deltas: channel-major
        float d0 = rm[(7 * a + 0) * WL + pix];
        float d1 = rm[(7 * a + 1) * WL + pix];
        float d2 = rm[(7 * a + 2) * WL + pix];
        float d3 = rm[(7 * a + 3) * WL + pix];
        float d4 = rm[(7 * a + 4) * WL + pix];
        float d5 = rm[(7 * a + 5) * WL + pix];
        float d6 = rm[(7 * a + 6) * WL + pix];

        // anchors: contiguous 7 floats
        float a0 = A[7 * a + 0], a1 = A[7 * a + 1], a2 = A[7 * a + 2];
        float a3 = A[7 * a + 3], a4 = A[7 * a + 4], a5 = A[7 * a + 5];
        float a6 = A[7 * a + 6];

        // decode
        float dg = sqrtf(a4 * a4 + a5 * a5);
        float X = fmaf(d0, dg, a0);
        float Y = fmaf(d1, dg, a1);
        float Z = fmaf(d2, a3, a2);
        float hh = __expf(d3) * a3;
        float ww = __expf(d4) * a4;
        float ll = __expf(d5) * a5;
        float yaw = d6 + a6;

        float c, s;
        __sincosf(yaw, &s, &c);

        // projected standup-2D closed form:
        // proj_x = T00*(X+rx) + T01*(Y+ry) + T02*(Z+rz) + T03
        // rx = cx*c - cy*s, ry = cx*s + cy*c, rz = cz, signs independent
        float bx = fmaf(T00, X, fmaf(T01, Y, fmaf(T02, Z, T03)));
        float by = fmaf(T10, X, fmaf(T11, Y, fmaf(T12, Z, T13)));
        float ex = 0.5f * (fabsf(fmaf(T00, c,  T01 * s)) * ll +
                           fabsf(fmaf(T01, c, -T00 * s)) * ww +
                           fabsf(T02) * hh);
        float ey = 0.5f * (fabsf(fmaf(T10, c,  T11 * s)) * ll +
                           fabsf(fmaf(T11, c, -T10 * s)) * ww +
                           fabsf(T12) * hh);

        px1[a] = bx - ex;  px2[a] = bx + ex;
        py1[a] = by - ey;  py2[a] = by + ey;
        area_t[a] = (2.0f * ex) * (2.0f * ey);
        wlog[a] = (prob > 0.1f) ? __logf(1.0f - prob) : 0.0f;
    }

    float s0 = 0.0f, s1 = 0.0f;
#pragma unroll 4
    for (int m = 0; m < NTGT; m++) {
        float4 tb = st_box[m];
        float ta = st_area[m];
        {
            float wi = fminf(px2[0], tb.z) - fmaxf(px1[0], tb.x);
            float hi = fminf(py2[0], tb.w) - fmaxf(py1[0], tb.y);
            if (wi > 0.0f && hi > 0.0f) {
                float wh = wi * hi;
                s0 += __fdividef(wh, area_t[0] + ta - wh);
            }
        }
        {
            float wi = fminf(px2[1], tb.z) - fmaxf(px1[1], tb.x);
            float hi = fminf(py2[1], tb.w) - fmaxf(py1[1], tb.y);
            if (wi > 0.0f && hi > 0.0f) {
                float wh = wi * hi;
                s1 += __fdividef(wh, area_t[1] + ta - wh);
            }
        }
    }

    float local = wlog[0] * s0 + wlog[1] * s1;

    // block reduction (all terms <= 0: no cancellation, fp32 partials are safe)
    __shared__ float red[8];
#pragma unroll
    for (int off = 16; off > 0; off >>= 1)
        local += __shfl_down_sync(0xFFFFFFFFu, local, off);
    int lane = threadIdx.x & 31;
    int wid  = threadIdx.x >> 5;
    if (lane == 0) red[wid] = local;
    __syncthreads();
    if (wid == 0) {
        float v = (lane < 8) ? red[lane] : 0.0f;
#pragma unroll
        for (int off = 4; off > 0; off >>= 1)
            v += __shfl_down_sync(0xFFFFFFFFu, v, off);
        if (lane == 0) atomicAdd(&g_accum, (double)v);
    }
}

// ---------------------------------------------------------------------------
// Kernel 3: finalize
// ---------------------------------------------------------------------------
__global__ void finalize_kernel(float* __restrict__ out) {
    out[0] = (float)g_accum;
}

extern "C" void kernel_launch(void* const* d_in, const int* in_sizes, int n_in,
                              void* d_out, int out_size) {
    const float* psm = (const float*)d_in[0];
    const float* rm  = (const float*)d_in[1];
    const float* anc = (const float*)d_in[2];
    const float* Tm  = (const float*)d_in[3];
    const float* tgt = (const float*)d_in[4];
    float* out = (float*)d_out;

    prep_kernel<<<1, 64>>>(tgt);
    loss_kernel<<<WL / 256, 256>>>(psm, rm, anc, Tm);
    finalize_kernel<<<1, 1>>>(out);
}

// round 2
// speedup vs baseline: 1.8777x; 1.8777x over previous
#include <cuda_runtime.h>
#include <math.h>

#define WDIM 512
#define LDIM 512
#define WL   (WDIM * LDIM)     // 262144 pixels
#define NTGT 64
#define TILE 16                 // 16x16 pixel tiles
#define TPB  (TILE * TILE)      // 256 threads
#define NBLK ((WDIM / TILE) * (LDIM / TILE))   // 1024 blocks

__device__ float g_part[NBLK];

// ---------------------------------------------------------------------------
// Main kernel: one 16x16 pixel tile per block, both anchors fused per thread.
// Per-block target culling against the block's pred-box bounding box.
// ---------------------------------------------------------------------------
__global__ __launch_bounds__(TPB) void loss_kernel(
    const float* __restrict__ psm,    // [2, W, L]
    const float* __restrict__ rm,     // [14, W, L]
    const float* __restrict__ anc,    // [W, L, 2, 7]
    const float* __restrict__ Tm,     // [4, 4]
    const float* __restrict__ target) // [64, 7]
{
    const int tid = threadIdx.x;

    // ---- tile -> pixel mapping ----
    const int tile_i = blockIdx.x >> 5;          // /32
    const int tile_j = blockIdx.x & 31;
    const int i = tile_i * TILE + (tid >> 4);
    const int j = tile_j * TILE + (tid & 15);
    const int pix = i * LDIM + j;

    // ---- target standup boxes (threads 0..63, kept in registers) ----
    float tminx = 0.f, tminy = 0.f, tmaxx = 0.f, tmaxy = 0.f, tarea = 0.f;
    if (tid < NTGT) {
        const float* t = target + tid * 7;
        float X = t[0], Y = t[1];
        float w = t[4], l = t[5];
        float c, s;
        __sincosf(t[6], &s, &c);
        float ex = 0.5f * (fabsf(c) * l + fabsf(s) * w);
        float ey = 0.5f * (fabsf(s) * l + fabsf(c) * w);
        tminx = X - ex;  tmaxx = X + ex;
        tminy = Y - ey;  tmaxy = Y + ey;
        tarea = (2.0f * ex) * (2.0f * ey);
    }

    // ---- pred boxes for both anchors ----
    const float T00 = Tm[0], T01 = Tm[1], T02 = Tm[2], T03 = Tm[3];
    const float T10 = Tm[4], T11 = Tm[5], T12 = Tm[6], T13 = Tm[7];

    const float* A = anc + (size_t)pix * 14;

    float px1[2], py1[2], px2[2], py2[2], area_t[2], wlog[2];

#pragma unroll
    for (int a = 0; a < 2; a++) {
        float xlogit = psm[a * WL + pix];
        float prob = 1.0f / (1.0f + __expf(-xlogit));

        float d0 = rm[(7 * a + 0) * WL + pix];
        float d1 = rm[(7 * a + 1) * WL + pix];
        float d2 = rm[(7 * a + 2) * WL + pix];
        float d3 = rm[(7 * a + 3) * WL + pix];
        float d4 = rm[(7 * a + 4) * WL + pix];
        float d5 = rm[(7 * a + 5) * WL + pix];
        float d6 = rm[(7 * a + 6) * WL + pix];

        float a0 = A[7 * a + 0], a1 = A[7 * a + 1], a2 = A[7 * a + 2];
        float a3 = A[7 * a + 3], a4 = A[7 * a + 4], a5 = A[7 * a + 5];
        float a6 = A[7 * a + 6];

        float dg = sqrtf(a4 * a4 + a5 * a5);
        float X = fmaf(d0, dg, a0);
        float Y = fmaf(d1, dg, a1);
        float Z = fmaf(d2, a3, a2);
        float hh = __expf(d3) * a3;
        float ww = __expf(d4) * a4;
        float ll = __expf(d5) * a5;

        float c, s;
        __sincosf(d6 + a6, &s, &c);

        float bx = fmaf(T00, X, fmaf(T01, Y, fmaf(T02, Z, T03)));
        float by = fmaf(T10, X, fmaf(T11, Y, fmaf(T12, Z, T13)));
        float ex = 0.5f * (fabsf(fmaf(T00, c,  T01 * s)) * ll +
                           fabsf(fmaf(T01, c, -T00 * s)) * ww +
                           fabsf(T02) * hh);
        float ey = 0.5f * (fabsf(fmaf(T10, c,  T11 * s)) * ll +
                           fabsf(fmaf(T11, c, -T10 * s)) * ww +
                           fabsf(T12) * hh);

        px1[a] = bx - ex;  px2[a] = bx + ex;
        py1[a] = by - ey;  py2[a] = by + ey;
        area_t[a] = (2.0f * ex) * (2.0f * ey);
        wlog[a] = (prob > 0.1f) ? __logf(1.0f - prob) : 0.0f;
    }

    // ---- block bounding box over all pred boxes (both anchors) ----
    float bminx = fminf(px1[0], px1[1]);
    float bminy = fminf(py1[0], py1[1]);
    float bmaxx = fmaxf(px2[0], px2[1]);
    float bmaxy = fmaxf(py2[0], py2[1]);

    __shared__ float s_minx[8], s_miny[8], s_maxx[8], s_maxy[8];
    __shared__ float s_bbox[4];
#pragma unroll
    for (int off = 16; off > 0; off >>= 1) {
        bminx = fminf(bminx, __shfl_xor_sync(0xFFFFFFFFu, bminx, off));
        bminy = fminf(bminy, __shfl_xor_sync(0xFFFFFFFFu, bminy, off));
        bmaxx = fmaxf(bmaxx, __shfl_xor_sync(0xFFFFFFFFu, bmaxx, off));
        bmaxy = fmaxf(bmaxy, __shfl_xor_sync(0xFFFFFFFFu, bmaxy, off));
    }
    const int lane = tid & 31;
    const int wid  = tid >> 5;
    if (lane == 0) {
        s_minx[wid] = bminx;  s_miny[wid] = bminy;
        s_maxx[wid] = bmaxx;  s_maxy[wid] = bmaxy;
    }
    __syncthreads();
    if (wid == 0) {
        float v0 = (lane < 8) ? s_minx[lane] :  1e30f;
        float v1 = (lane < 8) ? s_miny[lane] :  1e30f;
        float v2 = (lane < 8) ? s_maxx[lane] : -1e30f;
        float v3 = (lane < 8) ? s_maxy[lane] : -1e30f;
#pragma unroll
        for (int off = 4; off > 0; off >>= 1) {
            v0 = fminf(v0, __shfl_xor_sync(0xFFFFFFFFu, v0, off));
            v1 = fminf(v1, __shfl_xor_sync(0xFFFFFFFFu, v1, off));
            v2 = fmaxf(v2, __shfl_xor_sync(0xFFFFFFFFu, v2, off));
            v3 = fmaxf(v3, __shfl_xor_sync(0xFFFFFFFFu, v3, off));
        }
        if (lane == 0) {
            s_bbox[0] = v0;  s_bbox[1] = v1;  s_bbox[2] = v2;  s_bbox[3] = v3;
        }
    }
    __syncthreads();

    // ---- cull targets against block bbox, compact survivors to shared ----
    __shared__ int    s_cnt;
    __shared__ float4 s_cbox[NTGT];
    __shared__ float  s_carea[NTGT];
    if (tid == 0) s_cnt = 0;
    __syncthreads();
    if (tid < NTGT) {
        bool hit = (tminx <= s_bbox[2]) && (tmaxx >= s_bbox[0]) &&
                   (tminy <= s_bbox[3]) && (tmaxy >= s_bbox[1]);
        if (hit) {
            int idx = atomicAdd(&s_cnt, 1);
            s_cbox[idx]  = make_float4(tminx, tminy, tmaxx, tmaxy);
            s_carea[idx] = tarea;
        }
    }
    __syncthreads();
    const int cnt = s_cnt;

    // ---- IoU accumulation over surviving targets only ----
    float s0 = 0.0f, s1 = 0.0f;
    for (int m = 0; m < cnt; m++) {
        float4 tb = s_cbox[m];
        float ta = s_carea[m];
        {
            float wi = fminf(px2[0], tb.z) - fmaxf(px1[0], tb.x);
            float hi = fminf(py2[0], tb.w) - fmaxf(py1[0], tb.y);
            if (wi > 0.0f && hi > 0.0f) {
                float wh = wi * hi;
                s0 += __fdividef(wh, area_t[0] + ta - wh);
            }
        }
        {
            float wi = fminf(px2[1], tb.z) - fmaxf(px1[1], tb.x);
            float hi = fminf(py2[1], tb.w) - fmaxf(py1[1], tb.y);
            if (wi > 0.0f && hi > 0.0f) {
                float wh = wi * hi;
                s1 += __fdividef(wh, area_t[1] + ta - wh);
            }
        }
    }

    float local = wlog[0] * s0 + wlog[1] * s1;

    // ---- block sum reduction -> per-block partial (no atomics) ----
    __shared__ float red[8];
#pragma unroll
    for (int off = 16; off > 0; off >>= 1)
        local += __shfl_down_sync(0xFFFFFFFFu, local, off);
    if (lane == 0) red[wid] = local;
    __syncthreads();
    if (wid == 0) {
        float v = (lane < 8) ? red[lane] : 0.0f;
#pragma unroll
        for (int off = 4; off > 0; off >>= 1)
            v += __shfl_down_sync(0xFFFFFFFFu, v, off);
        if (lane == 0) g_part[blockIdx.x] = v;
    }
}

// ---------------------------------------------------------------------------
// Finalize: reduce 1024 per-block partials to the scalar output.
// ---------------------------------------------------------------------------
__global__ __launch_bounds__(1024) void finalize_kernel(float* __restrict__ out) {
    int tid = threadIdx.x;
    float v = g_part[tid];
    __shared__ float red[32];
#pragma unroll
    for (int off = 16; off > 0; off >>= 1)
        v += __shfl_down_sync(0xFFFFFFFFu, v, off);
    int lane = tid & 31, wid = tid >> 5;
    if (lane == 0) red[wid] = v;
    __syncthreads();
    if (wid == 0) {
        float s = red[lane];
#pragma unroll
        for (int off = 16; off > 0; off >>= 1)
            s += __shfl_down_sync(0xFFFFFFFFu, s, off);
        if (lane == 0) out[0] = s;
    }
}

extern "C" void kernel_launch(void* const* d_in, const int* in_sizes, int n_in,
                              void* d_out, int out_size) {
    const float* psm = (const float*)d_in[0];
    const float* rm  = (const float*)d_in[1];
    const float* anc = (const float*)d_in[2];
    const float* Tm  = (const float*)d_in[3];
    const float* tgt = (const float*)d_in[4];
    float* out = (float*)d_out;

    loss_kernel<<<NBLK, TPB>>>(psm, rm, anc, Tm, tgt);
    finalize_kernel<<<1, 1024>>>(out);
}